// round 17
// baseline (speedup 1.0000x reference)
#include <cuda_runtime.h>
#include <cuda_fp16.h>

#define NN 50000
#define DD 128
#define EE 800000

// Scratch (__device__ globals; no allocations allowed)
__device__ __align__(16) __half g_hh1[NN * DD]; // layer-1 h (fp16)
__device__ __align__(16) __half g_hh2[NN * DD]; // layer-2 h (fp16)
__device__ __align__(16) __half g_z16[NN * DD]; // layer-1 activation (fp16)
__device__ float  g_dinv  [NN];
__device__ float  g_degacc[NN];                 // zero-invariant between calls
__device__ int    g_cnt   [NN];                 // zero-invariant between calls
__device__ int    g_rowptr[NN + 1];
__device__ int    g_cursor[NN];
__device__ int2   g_sd    [EE];
__device__ int2   g_edge  [EE];                 // CSR-ordered (src, dinv[s]*ew bits)
__device__ int    g_bsum  [64];
__device__ int    g_boff  [64];
__device__ int    g_done;
__device__ int    g_flag;
__device__ int    g_is64;
__device__ __align__(16) __half g_w1t[DD * DD]; // W1^T fp16 [n][k]
__device__ __align__(16) __half g_w2t[DD * DD]; // W2^T fp16 [n][k]

// -------- detect dtype + reset scan flags (1 warp) --------
__global__ void k_detect(const int* __restrict__ ei32) {
    if (threadIdx.x == 0) {
        int acc = 0;
#pragma unroll
        for (int k = 0; k < 64; ++k) acc |= ei32[2 * k + 1];
        g_is64 = (acc == 0) ? 1 : 0;
        g_done = 0;
        g_flag = 0;
    }
}

// ---------------- transpose W1/W2 to fp16 [n][k] ----------------
__global__ void k_prepw(const float* __restrict__ W1,
                        const float* __restrict__ W2) {
    int i = blockIdx.x * blockDim.x + threadIdx.x;
    if (i >= DD * DD) return;
    int k = i >> 7;
    int n = i & 127;
    g_w1t[n * DD + k] = __float2half(W1[i]);
    g_w2t[n * DD + k] = __float2half(W2[i]);
}

// ---- convert + degree + histogram (1 edge/thread; degacc/cnt zero-invariant) ----
__global__ void k_convert(const int* __restrict__ ei32,
                          const float* __restrict__ ew, int E) {
    int e = blockIdx.x * blockDim.x + threadIdx.x;
    if (e >= E) return;
    int s, d;
    if (g_is64) {
        const int2* p = (const int2*)ei32;   // int64 little-endian: .x = low word
        s = p[e].x;
        d = p[E + e].x;
    } else {
        s = ei32[e];
        d = ei32[E + e];
    }
    g_sd[e] = make_int2(s, d);
    atomicAdd(&g_degacc[d], ew[e]);
    atomicAdd(&g_cnt[d], 1);
}

// ------- fused scan (last-block pattern) + dinv finalize + re-zero invariants -------
__global__ void k_scan_fused(int N) {
    __shared__ int wsum[32];
    int nb   = gridDim.x;
    int b    = blockIdx.x;
    int tid  = threadIdx.x;
    int lane = tid & 31;
    int wid  = tid >> 5;
    int i = b * 1024 + tid;
    int v = (i < N) ? g_cnt[i] : 0;

    int s = v;
#pragma unroll
    for (int o = 1; o < 32; o <<= 1) {
        int t = __shfl_up_sync(0xFFFFFFFFu, s, o);
        if (lane >= o) s += t;
    }
    if (lane == 31) wsum[wid] = s;
    __syncthreads();
    if (wid == 0) {
        int ws = wsum[lane];
#pragma unroll
        for (int o = 1; o < 32; o <<= 1) {
            int t = __shfl_up_sync(0xFFFFFFFFu, ws, o);
            if (lane >= o) ws += t;
        }
        wsum[lane] = ws;
    }
    __syncthreads();

    if (tid == 0) {
        g_bsum[b] = wsum[31];
        __threadfence();
        int t = atomicAdd(&g_done, 1);
        if (t == nb - 1) {
            int run = 0;
            for (int j = 0; j < nb; ++j) {
                int bs = atomicAdd(&g_bsum[j], 0);
                g_boff[j] = run;
                run += bs;
            }
            g_rowptr[N] = run;
            __threadfence();
            atomicExch(&g_flag, 1);
        }
    }
    if (tid == 0) {
        while (atomicAdd(&g_flag, 0) == 0) __nanosleep(64);
    }
    __syncthreads();
    int excl = s - v + ((wid > 0) ? wsum[wid - 1] : 0) + g_boff[b];
    if (i < N) {
        g_rowptr[i] = excl;
        g_cursor[i] = excl;
        float deg = g_degacc[i] + 1.0f;      // + self-loop weight
        g_dinv[i] = rsqrtf(deg);             // deg >= 1 > 0 always
        g_degacc[i] = 0.0f;                  // restore zero-invariant
        g_cnt[i] = 0;                        // restore zero-invariant
    }
}

// -------- place edges (1 edge/thread; record = (src, dinv[s]*ew)) --------
__global__ void k_place(const float* __restrict__ ew, int E) {
    int e = blockIdx.x * blockDim.x + threadIdx.x;
    if (e >= E) return;
    int2 sd = g_sd[e];
    float wse = g_dinv[sd.x] * ew[e];
    int pos = atomicAdd(&g_cursor[sd.y], 1);
    g_edge[pos] = make_int2(sd.x, __float_as_int(wse));
}

// ---------------- fp16 MMA macro (m16n8k16, fp32 accum) ----------------
#define MMA_F16(d, a0, a1, a2, a3, b0, b1)                                    \
    asm volatile(                                                             \
        "mma.sync.aligned.m16n8k16.row.col.f32.f16.f16.f32 "                  \
        "{%0,%1,%2,%3}, {%4,%5,%6,%7}, {%8,%9}, {%0,%1,%2,%3};"               \
        : "+f"(d[0]), "+f"(d[1]), "+f"(d[2]), "+f"(d[3])                      \
        : "r"(a0), "r"(a1), "r"(a2), "r"(a3), "r"(b0), "r"(b1))

// ------- GEMM: hh_dst = fp16(X @ W) via fp16 tensor-core mma -------
__global__ void __launch_bounds__(256)
k_gemm(const float* __restrict__ Xext, int use_gz, int dst2, int N) {
    __shared__ __half xs[128][24];
    __shared__ __half ws[128][24];

    const __half* __restrict__ Wt = use_gz ? g_w2t : g_w1t;
    __half* __restrict__ H = dst2 ? g_hh2 : g_hh1;

    int tid  = threadIdx.x;
    int lane = tid & 31;
    int warp = tid >> 5;
    int grp  = lane >> 2;
    int tig  = lane & 3;
    int wm   = warp & 3;
    int wn   = warp >> 2;
    int r0   = blockIdx.x * 128;

    float acc[2][8][4];
#pragma unroll
    for (int mt = 0; mt < 2; ++mt)
#pragma unroll
        for (int nt = 0; nt < 8; ++nt)
#pragma unroll
            for (int c = 0; c < 4; ++c) acc[mt][nt][c] = 0.0f;

    for (int chunk = 0; chunk < 8; ++chunk) {
        int k0 = chunk * 16;
        {
            int row  = tid >> 1;
            int part = (tid & 1) * 8;
            if (use_gz) {
                uint4 v = make_uint4(0u, 0u, 0u, 0u);
                if (r0 + row < N)
                    v = *(const uint4*)&g_z16[(r0 + row) * DD + k0 + part];
                *(uint4*)&xs[row][part] = v;
            } else {
                float4 v0 = make_float4(0.f, 0.f, 0.f, 0.f), v1 = v0;
                if (r0 + row < N) {
                    v0 = *(const float4*)&Xext[(r0 + row) * DD + k0 + part];
                    v1 = *(const float4*)&Xext[(r0 + row) * DD + k0 + part + 4];
                }
                __half2* dst = (__half2*)&xs[row][part];
                dst[0] = __floats2half2_rn(v0.x, v0.y);
                dst[1] = __floats2half2_rn(v0.z, v0.w);
                dst[2] = __floats2half2_rn(v1.x, v1.y);
                dst[3] = __floats2half2_rn(v1.z, v1.w);
            }
            *(uint4*)&ws[row][part] = *(const uint4*)&Wt[row * DD + k0 + part];
        }
        __syncthreads();

        unsigned a[2][4];
#pragma unroll
        for (int mt = 0; mt < 2; ++mt) {
            int ar = wm * 32 + mt * 16 + grp;
            a[mt][0] = *(const unsigned*)&xs[ar    ][2 * tig    ];
            a[mt][1] = *(const unsigned*)&xs[ar + 8][2 * tig    ];
            a[mt][2] = *(const unsigned*)&xs[ar    ][2 * tig + 8];
            a[mt][3] = *(const unsigned*)&xs[ar + 8][2 * tig + 8];
        }
#pragma unroll
        for (int nt = 0; nt < 8; ++nt) {
            int n = wn * 64 + nt * 8 + grp;
            unsigned b0 = *(const unsigned*)&ws[n][2 * tig    ];
            unsigned b1 = *(const unsigned*)&ws[n][2 * tig + 8];
            MMA_F16(acc[0][nt], a[0][0], a[0][1], a[0][2], a[0][3], b0, b1);
            MMA_F16(acc[1][nt], a[1][0], a[1][1], a[1][2], a[1][3], b0, b1);
        }
        __syncthreads();
    }

#pragma unroll
    for (int mt = 0; mt < 2; ++mt) {
#pragma unroll
        for (int nt = 0; nt < 8; ++nt) {
            int row = r0 + wm * 32 + mt * 16 + grp;
            int col = wn * 64 + nt * 8 + 2 * tig;
            if (row < N)
                *(__half2*)&H[row * DD + col] =
                    __floats2half2_rn(acc[mt][nt][0], acc[mt][nt][1]);
            if (row + 8 < N)
                *(__half2*)&H[(row + 8) * DD + col] =
                    __floats2half2_rn(acc[mt][nt][2], acc[mt][nt][3]);
        }
    }
}

// -------- paired-edge aggregate: warp = node, 16-lane halves each gather a full
// 256B row (uint4/lane) for a different edge of a pair; shfl.xor(16) combines. --------
__global__ void k_aggregate(const float* __restrict__ b,
                            const float* __restrict__ a,
                            float* __restrict__ Oext, int use_ext, int src2, int N) {
    int node = (blockIdx.x * blockDim.x + threadIdx.x) >> 5;
    if (node >= N) return;
    int lane = threadIdx.x & 31;
    int half = lane >> 4;    // 0/1: which edge of the pair
    int sub  = lane & 15;    // column group: 8 halfs per lane

    const uint4* __restrict__ hh = src2 ? (const uint4*)g_hh2 : (const uint4*)g_hh1;
    float di = g_dinv[node];

    uint4 ps = hh[node * 16 + sub];   // self row (broadcast across halves)

    float acc[8];
#pragma unroll
    for (int j = 0; j < 8; ++j) acc[j] = 0.f;

    int i   = g_rowptr[node];
    int end = g_rowptr[node + 1];

    // 4 pairs (8 edges) per iteration
    while (i + 8 <= end) {
        int2  ee[4];
        uint4 pp[4];
#pragma unroll
        for (int u = 0; u < 4; ++u) ee[u] = g_edge[i + 2 * u + half];
#pragma unroll
        for (int u = 0; u < 4; ++u) pp[u] = hh[ee[u].x * 16 + sub];
#pragma unroll
        for (int u = 0; u < 4; ++u) {
            float w = __int_as_float(ee[u].y);
            float2 f0 = __half22float2(*(__half2*)&pp[u].x);
            float2 f1 = __half22float2(*(__half2*)&pp[u].y);
            float2 f2 = __half22float2(*(__half2*)&pp[u].z);
            float2 f3 = __half22float2(*(__half2*)&pp[u].w);
            acc[0] = fmaf(w, f0.x, acc[0]); acc[1] = fmaf(w, f0.y, acc[1]);
            acc[2] = fmaf(w, f1.x, acc[2]); acc[3] = fmaf(w, f1.y, acc[3]);
            acc[4] = fmaf(w, f2.x, acc[4]); acc[5] = fmaf(w, f2.y, acc[5]);
            acc[6] = fmaf(w, f3.x, acc[6]); acc[7] = fmaf(w, f3.y, acc[7]);
        }
        i += 8;
    }
    // remaining full pairs
    while (i + 2 <= end) {
        int2 e = g_edge[i + half];
        uint4 p = hh[e.x * 16 + sub];
        float w = __int_as_float(e.y);
        float2 f0 = __half22float2(*(__half2*)&p.x);
        float2 f1 = __half22float2(*(__half2*)&p.y);
        float2 f2 = __half22float2(*(__half2*)&p.z);
        float2 f3 = __half22float2(*(__half2*)&p.w);
        acc[0] = fmaf(w, f0.x, acc[0]); acc[1] = fmaf(w, f0.y, acc[1]);
        acc[2] = fmaf(w, f1.x, acc[2]); acc[3] = fmaf(w, f1.y, acc[3]);
        acc[4] = fmaf(w, f2.x, acc[4]); acc[5] = fmaf(w, f2.y, acc[5]);
        acc[6] = fmaf(w, f3.x, acc[6]); acc[7] = fmaf(w, f3.y, acc[7]);
        i += 2;
    }
    // odd leftover edge: half 0 only
    if (i < end && half == 0) {
        int2 e = g_edge[i];
        uint4 p = hh[e.x * 16 + sub];
        float w = __int_as_float(e.y);
        float2 f0 = __half22float2(*(__half2*)&p.x);
        float2 f1 = __half22float2(*(__half2*)&p.y);
        float2 f2 = __half22float2(*(__half2*)&p.z);
        float2 f3 = __half22float2(*(__half2*)&p.w);
        acc[0] = fmaf(w, f0.x, acc[0]); acc[1] = fmaf(w, f0.y, acc[1]);
        acc[2] = fmaf(w, f1.x, acc[2]); acc[3] = fmaf(w, f1.y, acc[3]);
        acc[4] = fmaf(w, f2.x, acc[4]); acc[5] = fmaf(w, f2.y, acc[5]);
        acc[6] = fmaf(w, f3.x, acc[6]); acc[7] = fmaf(w, f3.y, acc[7]);
    }

    // combine halves
#pragma unroll
    for (int j = 0; j < 8; ++j)
        acc[j] += __shfl_xor_sync(0xFFFFFFFFu, acc[j], 16);

    if (half == 0) {
        float di2 = di * di;
        float2 s0 = __half22float2(*(__half2*)&ps.x);
        float2 s1 = __half22float2(*(__half2*)&ps.y);
        float2 s2h = __half22float2(*(__half2*)&ps.z);
        float2 s3 = __half22float2(*(__half2*)&ps.w);
        float sv[8] = {s0.x, s0.y, s1.x, s1.y, s2h.x, s2h.y, s3.x, s3.y};
        float4 b0 = ((const float4*)b)[sub * 2];
        float4 b1 = ((const float4*)b)[sub * 2 + 1];
        float4 a0 = ((const float4*)a)[sub * 2];
        float4 a1 = ((const float4*)a)[sub * 2 + 1];
        float bbv[8] = {b0.x, b0.y, b0.z, b0.w, b1.x, b1.y, b1.z, b1.w};
        float aav[8] = {a0.x, a0.y, a0.z, a0.w, a1.x, a1.y, a1.z, a1.w};
        float v[8];
#pragma unroll
        for (int j = 0; j < 8; ++j) {
            v[j] = fmaf(di, acc[j], fmaf(di2, sv[j], bbv[j]));
            v[j] = (v[j] > 0.f) ? v[j] : aav[j] * v[j];
        }
        if (use_ext) {
            ((float4*)Oext)[node * 32 + sub * 2]     = make_float4(v[0], v[1], v[2], v[3]);
            ((float4*)Oext)[node * 32 + sub * 2 + 1] = make_float4(v[4], v[5], v[6], v[7]);
        } else {
            uint4 pz;
            *(__half2*)&pz.x = __floats2half2_rn(v[0], v[1]);
            *(__half2*)&pz.y = __floats2half2_rn(v[2], v[3]);
            *(__half2*)&pz.z = __floats2half2_rn(v[4], v[5]);
            *(__half2*)&pz.w = __floats2half2_rn(v[6], v[7]);
            ((uint4*)g_z16)[node * 16 + sub] = pz;
        }
    }
}

// -------- launch --------
extern "C" void kernel_launch(void* const* d_in, const int* in_sizes, int n_in,
                              void* d_out, int out_size) {
    const float* x  = (const float*)d_in[0];
    const int*   ei = (const int*)d_in[1];
    const float* ew = (const float*)d_in[2];
    const float* W1 = (const float*)d_in[3];
    const float* b1 = (const float*)d_in[4];
    const float* a1 = (const float*)d_in[5];
    const float* W2 = (const float*)d_in[6];
    const float* b2 = (const float*)d_in[7];
    const float* a2 = (const float*)d_in[8];
    float* out = (float*)d_out;

    const int N = in_sizes[0] / DD;   // 50000
    const int E = in_sizes[2];        // 800000
    const int nb = (N + 1023) / 1024; // 49

    cudaStream_t s2;
    cudaEvent_t evFork, evJoin;
    cudaStreamCreateWithFlags(&s2, cudaStreamNonBlocking);
    cudaEventCreateWithFlags(&evFork, cudaEventDisableTiming);
    cudaEventCreateWithFlags(&evJoin, cudaEventDisableTiming);

    const int gemm_tiles = (N + 127) / 128;       // 391
    const int agg_grid   = (N * 32 + 255) / 256;

    // fork: prep chain on s2
    cudaEventRecord(evFork, 0);
    cudaStreamWaitEvent(s2, evFork, 0);
    k_detect    <<<1, 32, 0, s2>>>(ei);
    k_convert   <<<(E + 255) / 256, 256, 0, s2>>>(ei, ew, E);
    k_scan_fused<<<nb, 1024, 0, s2>>>(N);
    k_place     <<<(E + 255) / 256, 256, 0, s2>>>(ew, E);
    cudaEventRecord(evJoin, s2);

    // concurrent on default stream: W prep + layer-1 GEMM (-> g_hh1)
    k_prepw<<<(DD * DD + 255) / 256, 256>>>(W1, W2);
    k_gemm<<<gemm_tiles, 256>>>(x, 0, 0, N);

    // join, then the dependent pipeline
    cudaStreamWaitEvent(0, evJoin, 0);
    k_aggregate<<<agg_grid, 256>>>(b1, a1, out, 0, 0, N);
    k_gemm<<<gemm_tiles, 256>>>(nullptr, 1, 1, N);
    k_aggregate<<<agg_grid, 256>>>(b2, a2, out, 1, 1, N);
}